// round 4
// baseline (speedup 1.0000x reference)
#include <cuda_runtime.h>
#include <cstdint>

// ---------------- problem constants (fixed-shape problem) ----------------
constexpr int NN   = 10000;  // nodes
constexpr int F1   = 64;     // hidden feat
constexpr int COUT = 16;     // classes

// GEMM1 tiling
constexpr int BM = 64;
constexpr int BN = 64;
constexpr int BK = 16;
constexpr int KSPLIT = 8;
constexpr int NCHUNK = NN / BK;      // 625 (exact)
constexpr int AS_LD  = 68;           // padded As row stride (floats)

// ---------------- device scratch (no allocation; NEVER passed from host) --
__device__ __align__(16) float g_deg[NN];
__device__ __align__(16) float g_dinv[NN];
__device__ __align__(16) float g_bufA[(size_t)NN * F1];          // GEMM outputs
__device__ __align__(16) float g_bufB[(size_t)NN * F1];          // aggregation outputs
__device__ __align__(16) float g_part[(size_t)KSPLIT * NN * F1]; // split-K partials

__device__ __forceinline__ int clampN(int v) {
    v = v < 0 ? 0 : v;
    return v < NN ? v : NN - 1;
}

// ---------------- degree / norm ----------------
__global__ void deg_init_kernel() {
    int i = blockIdx.x * blockDim.x + threadIdx.x;
    if (i < NN) g_deg[i] = 1.0f;  // self-loop
}

// edge_index is INT32 (JAX x64 disabled downgrades int64 -> int32)
__global__ void deg_count_kernel(const int* __restrict__ ei, int E) {
    int e = blockIdx.x * blockDim.x + threadIdx.x;
    if (e < E) {
        int dst = clampN(ei[E + e]);
        atomicAdd(&g_deg[dst], 1.0f);
    }
}

__global__ void dinv_kernel() {
    int i = blockIdx.x * blockDim.x + threadIdx.x;
    if (i < NN) g_dinv[i] = rsqrtf(g_deg[i]);  // deg >= 1 always
}

// ---------------- GEMM1: [NN, NN] x [NN, 64] -> g_part (split-K) ----------
// 256 threads, 4x4 micro-tile, register-prefetch double-buffered SMEM.
__global__ void __launch_bounds__(256) gemm1_kernel(const float* __restrict__ A,
                                                    const float* __restrict__ W) {
    __shared__ __align__(16) float As[2][BK][AS_LD];   // transposed: As[k][m]
    __shared__ __align__(16) float Bs[2][BK][BN];

    const int tid  = threadIdx.x;
    const int m0   = blockIdx.x * BM;
    const int part = blockIdx.y;

    // chunk range for this split (625 = 8*78 + 1)
    const int q = NCHUNK / KSPLIT;
    const int r = NCHUNK % KSPLIT;
    const int cBeg = part * q + (part < r ? part : r);
    const int cEnd = cBeg + q + (part < r ? 1 : 0);

    // loader mapping
    const int a_row = tid >> 2;          // 0..63 (m within tile)
    const int a_c   = (tid & 3) * 4;     // 0,4,8,12 (k within chunk)
    const int b_row = tid >> 4;          // 0..15 (k within chunk)
    const int b_c   = (tid & 15) * 4;    // 0..60 (n)

    // compute mapping
    const int tx = tid & 15;             // n group (4 cols)
    const int ty = tid >> 4;             // m group (4 rows)

    const int arow_g = (m0 + a_row < NN) ? (m0 + a_row) : (NN - 1);  // clamp
    const float* Aptr = A + (size_t)arow_g * NN + a_c;
    const float* Wptr = W + (size_t)b_row * BN + b_c;

    float acc[4][4] = {};

    // prologue: chunk cBeg
    float4 rA = *reinterpret_cast<const float4*>(Aptr + (size_t)cBeg * BK);
    float4 rB = *reinterpret_cast<const float4*>(Wptr + (size_t)cBeg * BK * BN);
    As[0][a_c + 0][a_row] = rA.x;
    As[0][a_c + 1][a_row] = rA.y;
    As[0][a_c + 2][a_row] = rA.z;
    As[0][a_c + 3][a_row] = rA.w;
    *reinterpret_cast<float4*>(&Bs[0][b_row][b_c]) = rB;
    __syncthreads();

    for (int c = cBeg; c < cEnd; ++c) {
        const int  buf     = (c - cBeg) & 1;
        const bool hasNext = (c + 1 < cEnd);
        if (hasNext) {
            rA = *reinterpret_cast<const float4*>(Aptr + (size_t)(c + 1) * BK);
            rB = *reinterpret_cast<const float4*>(Wptr + (size_t)(c + 1) * BK * BN);
        }
        #pragma unroll
        for (int kk = 0; kk < BK; ++kk) {
            const float4 av = *reinterpret_cast<const float4*>(&As[buf][kk][ty * 4]);
            const float4 bv = *reinterpret_cast<const float4*>(&Bs[buf][kk][tx * 4]);
            acc[0][0] += av.x * bv.x; acc[0][1] += av.x * bv.y; acc[0][2] += av.x * bv.z; acc[0][3] += av.x * bv.w;
            acc[1][0] += av.y * bv.x; acc[1][1] += av.y * bv.y; acc[1][2] += av.y * bv.z; acc[1][3] += av.y * bv.w;
            acc[2][0] += av.z * bv.x; acc[2][1] += av.z * bv.y; acc[2][2] += av.z * bv.z; acc[2][3] += av.z * bv.w;
            acc[3][0] += av.w * bv.x; acc[3][1] += av.w * bv.y; acc[3][2] += av.w * bv.z; acc[3][3] += av.w * bv.w;
        }
        if (hasNext) {
            const int nb = buf ^ 1;
            As[nb][a_c + 0][a_row] = rA.x;
            As[nb][a_c + 1][a_row] = rA.y;
            As[nb][a_c + 2][a_row] = rA.z;
            As[nb][a_c + 3][a_row] = rA.w;
            *reinterpret_cast<float4*>(&Bs[nb][b_row][b_c]) = rB;
            __syncthreads();
        }
    }

    float* outp = &g_part[(size_t)part * NN * F1];
    #pragma unroll
    for (int i = 0; i < 4; ++i) {
        const int row = m0 + ty * 4 + i;
        if (row < NN) {
            float4 v = make_float4(acc[i][0], acc[i][1], acc[i][2], acc[i][3]);
            *reinterpret_cast<float4*>(&outp[(size_t)row * F1 + tx * 4]) = v;
        }
    }
}

// reduce split-K partials -> g_bufA
__global__ void reduce_part_kernel() {
    int idx = blockIdx.x * blockDim.x + threadIdx.x;
    if (idx < NN * F1) {
        float s = 0.0f;
        #pragma unroll
        for (int p = 0; p < KSPLIT; ++p) s += g_part[(size_t)p * NN * F1 + idx];
        g_bufA[idx] = s;
    }
}

// ---------------- small GEMMs: g_bufB [NN,64] x W [64,C] -> g_bufA --------
template <int CIN, int C>
__global__ void gemm_small_kernel(const float* __restrict__ W) {
    __shared__ float w_s[CIN * C];
    for (int i = threadIdx.x; i < CIN * C; i += blockDim.x) w_s[i] = W[i];
    __syncthreads();

    const int total  = NN * C;
    const int stride = gridDim.x * blockDim.x;
    for (int idx = blockIdx.x * blockDim.x + threadIdx.x; idx < total; idx += stride) {
        const int row = idx / C;
        const int col = idx % C;
        const float* rp = &g_bufB[(size_t)row * CIN];
        float acc = 0.0f;
        #pragma unroll
        for (int k = 0; k < CIN; ++k) acc += rp[k] * w_s[k * C + col];
        g_bufA[idx] = acc;
    }
}

// ---------------- aggregation: g_bufA -> g_bufB ----------------
// init: self-loop contribution bufB[i][:] = bufA[i][:] * dinv[i]^2
template <int C>
__global__ void agg_init_kernel() {
    int idx = blockIdx.x * blockDim.x + threadIdx.x;
    if (idx < NN * C) {
        const int row = idx / C;
        const float d = g_dinv[row];
        g_bufB[idx] = g_bufA[idx] * d * d;
    }
}

// edges: one thread per (edge, 4-col group): float4 gather + 4 atomic adds
template <int C>
__global__ void agg_edges_kernel(const int* __restrict__ ei, int E) {
    constexpr int LPE = C / 4;
    const long long t = (long long)blockIdx.x * blockDim.x + threadIdx.x;
    if (t >= (long long)E * LPE) return;
    const int e = (int)(t / LPE);
    const int g = (int)(t % LPE);
    const int src = clampN(ei[e]);
    const int dst = clampN(ei[E + e]);
    const float norm = g_dinv[src] * g_dinv[dst];
    const float4 v = *reinterpret_cast<const float4*>(&g_bufA[(size_t)src * C + g * 4]);
    float* o = &g_bufB[(size_t)dst * C + g * 4];
    atomicAdd(o + 0, v.x * norm);
    atomicAdd(o + 1, v.y * norm);
    atomicAdd(o + 2, v.z * norm);
    atomicAdd(o + 3, v.w * norm);
}

// ---------------- epilogues (in-place on g_bufB) ----------------
template <int C>
__global__ void bias_relu_kernel(const float* __restrict__ b) {
    int idx = blockIdx.x * blockDim.x + threadIdx.x;
    if (idx < NN * C) {
        const float v = g_bufB[idx] + b[idx % C];
        g_bufB[idx] = v > 0.0f ? v : 0.0f;
    }
}

__global__ void softmax_kernel(const float* __restrict__ b, float* __restrict__ out) {
    int r = blockIdx.x * blockDim.x + threadIdx.x;
    if (r >= NN) return;
    float v[COUT];
    float m = -1e30f;
    #pragma unroll
    for (int j = 0; j < COUT; ++j) {
        v[j] = g_bufB[(size_t)r * COUT + j] + b[j];
        m = fmaxf(m, v[j]);
    }
    float s = 0.0f;
    #pragma unroll
    for (int j = 0; j < COUT; ++j) {
        v[j] = expf(v[j] - m);
        s += v[j];
    }
    const float inv = 1.0f / s;
    #pragma unroll
    for (int j = 0; j < COUT; ++j) out[(size_t)r * COUT + j] = v[j] * inv;
}

// ---------------- launch ----------------
extern "C" void kernel_launch(void* const* d_in, const int* in_sizes, int n_in,
                              void* d_out, int out_size) {
    const float* x  = (const float*)d_in[0];
    const int*   ei = (const int*)d_in[1];   // int32! (JAX x64 disabled)
    const float* W1 = (const float*)d_in[2];
    const float* b1 = (const float*)d_in[3];
    const float* W2 = (const float*)d_in[4];
    const float* b2 = (const float*)d_in[5];
    const float* W3 = (const float*)d_in[6];
    const float* b3 = (const float*)d_in[7];
    float* out = (float*)d_out;

    const int E = in_sizes[1] / 2;

    const int T = 256;
    const int gN   = (NN + T - 1) / T;
    const int gE   = (E + T - 1) / T;
    const int g64  = (NN * F1 + T - 1) / T;
    const int g16  = (NN * COUT + T - 1) / T;
    const int gE64 = (int)(((long long)E * (F1 / 4) + T - 1) / T);
    const int gE16 = (int)(((long long)E * (COUT / 4) + T - 1) / T);
    const dim3 gGemm1((NN + BM - 1) / BM, KSPLIT);   // 157 x 8

    // degrees + normalization (recomputed every call: deterministic)
    deg_init_kernel<<<gN, T>>>();
    deg_count_kernel<<<gE, T>>>(ei, E);
    dinv_kernel<<<gN, T>>>();

    // ---- layer 1 ----  (GEMM -> bufA, agg bufA->bufB, relu bufB)
    gemm1_kernel<<<gGemm1, T>>>(x, W1);
    reduce_part_kernel<<<g64, T>>>();
    agg_init_kernel<F1><<<g64, T>>>();
    agg_edges_kernel<F1><<<gE64, T>>>(ei, E);
    bias_relu_kernel<F1><<<g64, T>>>(b1);

    // ---- layer 2 ----  (small GEMM bufB->bufA, agg, relu)
    gemm_small_kernel<F1, F1><<<1480, T>>>(W2);
    agg_init_kernel<F1><<<g64, T>>>();
    agg_edges_kernel<F1><<<gE64, T>>>(ei, E);
    bias_relu_kernel<F1><<<g64, T>>>(b2);

    // ---- layer 3 ----
    gemm_small_kernel<F1, COUT><<<1480, T>>>(W3);
    agg_init_kernel<COUT><<<g16, T>>>();
    agg_edges_kernel<COUT><<<gE16, T>>>(ei, E);
    softmax_kernel<<<gN, T>>>(b3, out);
}